// round 16
// baseline (speedup 1.0000x reference)
#include <cuda_runtime.h>
#include <cuda_fp16.h>
#include <cstdint>

#define Bn   2
#define Nn   2048
#define CIN  128
#define Hh   16
#define Cc   8
#define HC   128
#define LOG2E 1.4426950408889634f
#define NJB  16          // j-blocks of 128

// smem (bytes): H 2x16384 | FF 2x4096 | adj fp16 2x4096  = 49152
#define SO_H    0
#define SH_STRIDE 16384
#define SO_FF   (2 * 16384)
#define SFF_STRIDE 4096
#define SO_A    (2 * 16384 + 2 * 4096)
#define SA_STRIDE 4096
#define SMEM_BYTES (2 * 16384 + 2 * 4096 + 2 * 4096)

// ---- device scratch ----
// g_hT3: per (b, jb): [kp 0..7: 4096B][f 0..127: 32B] (pair-interleaved words)
__device__ __half   g_hT3[Bn * HC * Nn];
__device__ float    g_lp [Bn * Nn * Hh];       // lp * log2e
// g_FF2: per (b,h): per 16-group (64B): [tig 0..3][8B Fa | 8B Fpa]
__device__ __half   g_FF2[Bn * Hh * Nn * 2];

// ---- PTX helpers ----
static __device__ __forceinline__ uint32_t s2u(const void* p) {
    return (uint32_t)__cvta_generic_to_shared(p);
}
static __device__ __forceinline__ float ex2f(float x) {
    float r; asm("ex2.approx.f32 %0, %1;" : "=f"(r) : "f"(x)); return r;
}
static __device__ __forceinline__ uint32_t packh2(float lo, float hi) {
    uint32_t d; asm("cvt.rn.f16x2.f32 %0, %1, %2;" : "=r"(d) : "f"(hi), "f"(lo)); return d;
}
static __device__ __forceinline__ uint32_t h2b(__half2 v) {
    return *reinterpret_cast<uint32_t*>(&v);
}
static __device__ __forceinline__ __half2 b2h(uint32_t u) {
    return *reinterpret_cast<__half2*>(&u);
}
static __device__ __forceinline__ void mma16816(float& d0, float& d1, float& d2, float& d3,
                                                uint32_t a0, uint32_t a1, uint32_t a2, uint32_t a3,
                                                uint32_t b0, uint32_t b1) {
    asm("mma.sync.aligned.m16n8k16.row.col.f32.f16.f16.f32 "
        "{%0,%1,%2,%3}, {%4,%5,%6,%7}, {%8,%9}, {%0,%1,%2,%3};"
        : "+f"(d0), "+f"(d1), "+f"(d2), "+f"(d3)
        : "r"(a0), "r"(a1), "r"(a2), "r"(a3), "r"(b0), "r"(b1));
}
#define CPA16(dst, src) asm volatile("cp.async.cg.shared.global [%0], [%1], 16;" :: "r"(dst), "l"(src))
#define CPA_COMMIT()    asm volatile("cp.async.commit_group;")
#define CPA_WAIT1()     asm volatile("cp.async.wait_group 1;")

// ---------------------------------------------------------------
// Kernel B: projection + per-node logits, fused.
// hT3 pair-interleaved; FF2 fragment-permuted interleaved.
// ---------------------------------------------------------------
__global__ __launch_bounds__(128) void k_proj(const float* __restrict__ nf,
                                              const float* __restrict__ W,
                                              const float* __restrict__ bias,
                                              const float* __restrict__ a) {
    __shared__ float snf[16][132];
    const int t  = threadIdx.x;
    const int r0 = blockIdx.x * 16;
#pragma unroll
    for (int r = 0; r < 16; ++r)
        snf[r][t] = nf[(size_t)(r0 + r) * CIN + t];
    __syncthreads();

    float acc[16];
    const float bv = bias[t];
#pragma unroll
    for (int r = 0; r < 16; ++r) acc[r] = bv;

    for (int k4 = 0; k4 < CIN / 4; ++k4) {
        const float w0 = W[(k4 * 4 + 0) * HC + t];
        const float w1 = W[(k4 * 4 + 1) * HC + t];
        const float w2 = W[(k4 * 4 + 2) * HC + t];
        const float w3 = W[(k4 * 4 + 3) * HC + t];
#pragma unroll
        for (int r = 0; r < 16; ++r) {
            const float4 s = *(const float4*)&snf[r][k4 * 4];
            acc[r] = fmaf(s.x, w0, acc[r]);
            acc[r] = fmaf(s.y, w1, acc[r]);
            acc[r] = fmaf(s.z, w2, acc[r]);
            acc[r] = fmaf(s.w, w3, acc[r]);
        }
    }

    const int b  = r0 >> 11;
    const int n0 = r0 & (Nn - 1);
    const int jb = n0 >> 7;
    const int kp = (n0 & 127) >> 4;        // kpair 0..7

    // hT3 write: pair-interleave words of chunks c0 (n 0..7) and c1 (n 8..15)
    {
        __half hv[16], iv[16];
#pragma unroll
        for (int r = 0; r < 16; ++r) hv[r] = __float2half(acc[r]);
#pragma unroll
        for (int w = 0; w < 4; ++w) {
            iv[4 * w + 0] = hv[2 * w];
            iv[4 * w + 1] = hv[2 * w + 1];
            iv[4 * w + 2] = hv[8 + 2 * w];
            iv[4 * w + 3] = hv[9 + 2 * w];
        }
        __half* base = g_hT3 + ((((size_t)(b * NJB + jb)) * 8 + kp) * 128 + t) * 16;
        *(uint4*)base       = *(const uint4*)&iv[0];
        *(uint4*)(base + 8) = *(const uint4*)&iv[8];
    }

    __syncthreads();
#pragma unroll
    for (int r = 0; r < 16; ++r)
        snf[r][t] = acc[r];                // snf now holds h
    __syncthreads();

    const int rr = t >> 3;                 // node-in-block 0..15
    const int hb = (t & 7) * 2;
    const int slot = (rr & 1) | (((rr >> 3) & 1) << 1) | (((rr >> 1) & 3) << 2);
    const int tigs = slot >> 2, pos = slot & 3;
    const int g = n0 >> 4;                 // 16-group index
#pragma unroll
    for (int p = 0; p < 2; ++p) {
        const int h = hb + p;
        const float* hv = &snf[rr][h * Cc];
        const float* ap = a + h * 2 * Cc;
        float lp = 0.f, lc = 0.f;
#pragma unroll
        for (int c = 0; c < Cc; ++c) {
            lp = fmaf(hv[c], ap[c],      lp);
            lc = fmaf(hv[c], ap[Cc + c], lc);
        }
        lp *= LOG2E; lc *= LOG2E;
        g_lp[(r0 + rr) * Hh + h] = lp;
        __half* fb = g_FF2 + (((size_t)b * Hh + h) * (Nn / 16) + g) * 32;
        fb[tigs * 8 + pos]     = __float2half(ex2f(lc));
        fb[tigs * 8 + 4 + pos] = __float2half(ex2f(0.2f * lc));
    }
}

// ---------------------------------------------------------------
// Kernel C: fused softmax-attention via mma.m16n8k16.
// All inner-loop operands in smem (cp.async double-buffered H + FF;
// adj fp32 register-pipelined -> fp16 smem). No TMA, no mbarrier.
// ---------------------------------------------------------------
__global__ __launch_bounds__(256, 4) void k_main(const float* __restrict__ adj,
                                                 float* __restrict__ out,
                                                 int copy_adj) {
    extern __shared__ __align__(128) char smem[];

    const int t    = threadIdx.x;
    const int warp = t >> 5;
    const int lane = t & 31;
    const int gid  = lane >> 2;   // 0..7
    const int tig  = lane & 3;    // 0..3

    const int bx = blockIdx.x;
    const int b  = bx >> 8;
    const int i0 = ((bx & 255) >> 1) * 16;
    const int hp = bx & 1;
    const int hh = hp * 8 + warp;
    const size_t bN = (size_t)b * Nn;

    // per-row factors, stabilized by m = leaky(lp)
    __half2 E0, E0p, E1, E1p;
    {
        const float lp0 = g_lp[(bN + i0 + gid)     * Hh + hh];
        const float lp1 = g_lp[(bN + i0 + gid + 8) * Hh + hh];
        const float m0 = fmaxf(lp0, 0.2f * lp0);
        const float m1 = fmaxf(lp1, 0.2f * lp1);
        E0  = __float2half2_rn(ex2f(lp0 - m0));
        E0p = __float2half2_rn(ex2f(0.2f * lp0 - m0));
        E1  = __float2half2_rn(ex2f(lp1 - m1));
        E1p = __float2half2_rn(ex2f(0.2f * lp1 - m1));
    }

    // cp.async source bases
    const char* Hsrc  = (const char*)g_hT3 + (size_t)(b * NJB) * 32768 + hp * 2048;
    const char* FFsrc = (const char*)g_FF2
        + ((size_t)(b * Hh + hp * 8 + (t >> 5))) * 8192 + (t & 31) * 16;

    // stage data(jb) into buffers (jb&1)
    auto stage = [&](int jb) {
        char* sHb  = smem + SO_H  + (jb & 1) * SH_STRIDE;
        char* sFFb = smem + SO_FF + (jb & 1) * SFF_STRIDE;
#pragma unroll
        for (int q = 0; q < 4; ++q) {
            const int c = q * 256 + t;
            const int kp = c >> 7, rem = c & 127;
            CPA16(s2u(sHb + c * 16), Hsrc + (size_t)jb * 32768 + kp * 4096 + rem * 16);
        }
        CPA16(s2u(sFFb + t * 16), FFsrc + (size_t)jb * 512);
    };

    // adj register pipeline
    const int av_row = t >> 4;
    const int av_col = (t & 15) * 4;
    const float* adjsrc = adj + (bN + i0 + av_row) * (size_t)Nn + av_col;
    const int do_tail = copy_adj && (hp == 0);
    float* tdst = out + (size_t)Bn * Nn * HC + (bN + i0 + av_row) * (size_t)Nn + av_col;

    // convert mapping (R15 formulas)
    const int cv_ks = (t & 15) >> 2;
    const uint32_t cv_b0 = (uint32_t)((t >> 4) * 32 + ((t & 1) * 2) * 8 + (((t >> 1) & 1)) * 4);

    float dn0 = 0.f, dn1 = 0.f, dn2 = 0.f, dn3 = 0.f;
    float dd0 = 0.f, dd1 = 0.f, dd2 = 0.f, dd3 = 0.f;
    const uint32_t ONES = 0x3C003C00u;

    // ---- prologue ----
    float4 v0 = *(const float4*)(adjsrc);
    float4 v1 = *(const float4*)(adjsrc + 64);
    stage(0);
    CPA_COMMIT();

    for (int jb = 0; jb < NJB; ++jb) {
        char* const sHb  = smem + SO_H  + (jb & 1) * SH_STRIDE;
        char* const sFFb = smem + SO_FF + (jb & 1) * SFF_STRIDE;
        char* const sAb  = smem + SO_A  + (jb & 1) * SA_STRIDE;

        // convert adj regs -> paired fp16 smem, + tail copy
        *(uint32_t*)(sAb + cv_ks * 512 + cv_b0)           = packh2(v0.x, v0.y);
        *(uint32_t*)(sAb + cv_ks * 512 + cv_b0 + 8)       = packh2(v0.z, v0.w);
        *(uint32_t*)(sAb + (cv_ks + 4) * 512 + cv_b0)     = packh2(v1.x, v1.y);
        *(uint32_t*)(sAb + (cv_ks + 4) * 512 + cv_b0 + 8) = packh2(v1.z, v1.w);
        if (do_tail) {
            *(float4*)(tdst + jb * 128)      = v0;
            *(float4*)(tdst + jb * 128 + 64) = v1;
        }
        __syncthreads();

        // prefetch next tile + next adj regs
        if (jb + 1 < NJB) {
            stage(jb + 1);
            CPA_COMMIT();
            v0 = *(const float4*)(adjsrc + (jb + 1) * 128);
            v1 = *(const float4*)(adjsrc + (jb + 1) * 128 + 64);
        } else {
            CPA_COMMIT();   // empty group keeps wait_group(1) semantics
        }
        CPA_WAIT1();        // data(jb) resident

        const char* Hp  = sHb + (warp * 8 + gid) * 32 + tig * 8;
        const char* Fj  = sFFb + warp * 512 + tig * 16;
        const char* Ap0 = sAb + gid * 32       + tig * 8;
        const char* Ap1 = sAb + (gid + 8) * 32 + tig * 8;

#pragma unroll
        for (int ks = 0; ks < 8; ++ks) {
            const uint4 ff = *(const uint4*)(Fj + ks * 64);
            const uint2 bh = *(const uint2*)(Hp + ks * 2048);
            const uint2 a0 = *(const uint2*)(Ap0 + ks * 512);
            const uint2 a1 = *(const uint2*)(Ap1 + ks * 512);

            const __half2 w0lo = __hmax2(__hmul2(b2h(ff.x), E0),  __hmul2(b2h(ff.z), E0p));
            const __half2 w1lo = __hmax2(__hmul2(b2h(ff.x), E1),  __hmul2(b2h(ff.z), E1p));
            const __half2 w0hi = __hmax2(__hmul2(b2h(ff.y), E0),  __hmul2(b2h(ff.w), E0p));
            const __half2 w1hi = __hmax2(__hmul2(b2h(ff.y), E1),  __hmul2(b2h(ff.w), E1p));

            const uint32_t ra0 = h2b(__hmul2(w0lo, b2h(a0.x)));
            const uint32_t ra1 = h2b(__hmul2(w1lo, b2h(a1.x)));
            const uint32_t ra2 = h2b(__hmul2(w0hi, b2h(a0.y)));
            const uint32_t ra3 = h2b(__hmul2(w1hi, b2h(a1.y)));

            mma16816(dn0, dn1, dn2, dn3, ra0, ra1, ra2, ra3, bh.x, bh.y);
            mma16816(dd0, dd1, dd2, dd3, ra0, ra1, ra2, ra3, ONES, ONES);
        }
    }

    // ---- epilogue: divide and store ----
    {
        const float inv0 = 1.0f / dd0;
        const float inv1 = 1.0f / dd2;
        float2 o0 = make_float2(dn0 * inv0, dn1 * inv0);
        float2 o1 = make_float2(dn2 * inv1, dn3 * inv1);
        *(float2*)(out + (bN + i0 + gid)     * HC + hh * Cc + 2 * tig) = o0;
        *(float2*)(out + (bN + i0 + gid + 8) * HC + hh * Cc + 2 * tig) = o1;
    }
}

// ---------------------------------------------------------------
extern "C" void kernel_launch(void* const* d_in, const int* in_sizes, int n_in,
                              void* d_out, int out_size) {
    const float* nf   = (const float*)d_in[0];
    const float* adj  = (const float*)d_in[1];
    const float* W    = (const float*)d_in[2];
    const float* bias = (const float*)d_in[3];
    const float* a    = (const float*)d_in[4];
    float* out = (float*)d_out;

    const long long outel = (long long)Bn * Nn * HC;        // 524288
    const long long adjel = (long long)Bn * Nn * Nn;        // 8388608
    const int copy_adj = ((long long)out_size >= outel + adjel) ? 1 : 0;

    cudaFuncSetAttribute(k_main, cudaFuncAttributeMaxDynamicSharedMemorySize,
                         SMEM_BYTES);

    k_proj<<<Bn * Nn / 16, 128>>>(nf, W, bias, a);
    k_main<<<Bn * 256, 256, SMEM_BYTES>>>(adj, out, copy_adj);
}

// round 17
// speedup vs baseline: 1.0555x; 1.0555x over previous
#include <cuda_runtime.h>
#include <cuda_fp16.h>
#include <cuda.h>
#include <cstdint>

#define Bn   2
#define Nn   2048
#define CIN  128
#define Hh   16
#define Cc   8
#define HC   128
#define LOG2E 1.4426950408889634f
#define NJB  16          // j-blocks of 128

// smem (bytes): adj fp32 ring 4x8192 | adj fp16 (paired layout) 2x4096
#define SO_F    0
#define SF_STRIDE 8192
#define SO_A    (4 * 8192)
#define SA_STRIDE 4096
#define SMEM_BYTES (4 * 8192 + 2 * 4096)
#define TILE_BYTES 8192          // per-stage expect_tx

// driver-API typedef (not provided by this toolchain's cudaTypedefs.h)
typedef CUresult (*PFN_tmencode)(
    CUtensorMap*, CUtensorMapDataType, cuuint32_t, void*,
    const cuuint64_t*, const cuuint64_t*, const cuuint32_t*, const cuuint32_t*,
    CUtensorMapInterleave, CUtensorMapSwizzle, CUtensorMapL2promotion,
    CUtensorMapFloatOOBfill);

// ---- device scratch ----
// g_hT3: per (b, jb): [kpair 0..7][f 0..127][32B: c0w0 c1w0 c0w1 c1w1 ...]
__device__ __half   g_hT3[Bn * HC * Nn];
__device__ float    g_lp [Bn * Nn * Hh];       // lp * log2e
// g_FF2: per (b,h): per 16-group: [tig 0..3][8B Fa slots | 8B Fpa slots]
__device__ __half   g_FF2[Bn * Hh * Nn * 2];

// ---- PTX helpers ----
static __device__ __forceinline__ uint32_t s2u(const void* p) {
    return (uint32_t)__cvta_generic_to_shared(p);
}
static __device__ __forceinline__ float ex2f(float x) {
    float r; asm("ex2.approx.f32 %0, %1;" : "=f"(r) : "f"(x)); return r;
}
static __device__ __forceinline__ uint32_t packh2(float lo, float hi) {
    uint32_t d; asm("cvt.rn.f16x2.f32 %0, %1, %2;" : "=r"(d) : "f"(hi), "f"(lo)); return d;
}
static __device__ __forceinline__ uint32_t h2b(__half2 v) {
    return *reinterpret_cast<uint32_t*>(&v);
}
static __device__ __forceinline__ __half2 b2h(uint32_t u) {
    return *reinterpret_cast<__half2*>(&u);
}
static __device__ __forceinline__ void mma16816(float& d0, float& d1, float& d2, float& d3,
                                                uint32_t a0, uint32_t a1, uint32_t a2, uint32_t a3,
                                                uint32_t b0, uint32_t b1) {
    asm("mma.sync.aligned.m16n8k16.row.col.f32.f16.f16.f32 "
        "{%0,%1,%2,%3}, {%4,%5,%6,%7}, {%8,%9}, {%0,%1,%2,%3};"
        : "+f"(d0), "+f"(d1), "+f"(d2), "+f"(d3)
        : "r"(a0), "r"(a1), "r"(a2), "r"(a3), "r"(b0), "r"(b1));
}
#define MBAR_INIT(mb, cnt) \
    asm volatile("mbarrier.init.shared.b64 [%0], %1;" :: "r"(mb), "r"(cnt) : "memory")
#define MBAR_EXPECT(mb, bytes) \
    asm volatile("mbarrier.arrive.expect_tx.shared.b64 _, [%0], %1;" :: "r"(mb), "r"(bytes) : "memory")
#define TMA2D(smem, map, x, y, mb) \
    asm volatile("cp.async.bulk.tensor.2d.shared::cta.global.tile.mbarrier::complete_tx::bytes " \
                 "[%0], [%1, {%2, %3}], [%4];" \
                 :: "r"(smem), "l"(map), "r"(x), "r"(y), "r"(mb) : "memory")
#define TMA2D_ST(map, x, y, smem) \
    asm volatile("cp.async.bulk.tensor.2d.global.shared::cta.tile.bulk_group " \
                 "[%0, {%1, %2}], [%3];" \
                 :: "l"(map), "r"(x), "r"(y), "r"(smem) : "memory")
#define TMA_ST_COMMIT() asm volatile("cp.async.bulk.commit_group;" ::: "memory")
#define TMA_ST_WAIT(n)  asm volatile("cp.async.bulk.wait_group %0;" :: "n"(n) : "memory")
static __device__ __forceinline__ void mbar_wait(uint32_t mb, uint32_t parity) {
    asm volatile(
        "{\n\t.reg .pred P;\n\t"
        "WL_%=:\n\t"
        "mbarrier.try_wait.parity.acquire.cta.shared::cta.b64 P, [%0], %1, 0x989680;\n\t"
        "@P bra.uni WD_%=;\n\t"
        "bra.uni WL_%=;\n\t"
        "WD_%=:\n\t}"
        :: "r"(mb), "r"(parity) : "memory");
}

// ---------------------------------------------------------------
// Kernel B: projection + per-node logits, fused.
// 256 threads: thread = (feature f, row-half); 8 accs/thread.
// hT3 pair-interleaved; FF2 fragment-permuted interleaved.
// ---------------------------------------------------------------
__global__ __launch_bounds__(256) void k_proj(const float* __restrict__ nf,
                                              const float* __restrict__ W,
                                              const float* __restrict__ bias,
                                              const float* __restrict__ a) {
    __shared__ float snf[16][132];
    const int t    = threadIdx.x;
    const int f    = t & 127;
    const int half = t >> 7;           // 0..1
    const int r0   = blockIdx.x * 16;

#pragma unroll
    for (int r = 0; r < 8; ++r)
        snf[half * 8 + r][f] = nf[(size_t)(r0 + half * 8 + r) * CIN + f];
    __syncthreads();

    float acc[8];
    const float bv = bias[f];
#pragma unroll
    for (int r = 0; r < 8; ++r) acc[r] = bv;

    for (int k4 = 0; k4 < CIN / 4; ++k4) {
        const float w0 = W[(k4 * 4 + 0) * HC + f];
        const float w1 = W[(k4 * 4 + 1) * HC + f];
        const float w2 = W[(k4 * 4 + 2) * HC + f];
        const float w3 = W[(k4 * 4 + 3) * HC + f];
#pragma unroll
        for (int r = 0; r < 8; ++r) {
            const float4 s = *(const float4*)&snf[half * 8 + r][k4 * 4];
            acc[r] = fmaf(s.x, w0, acc[r]);
            acc[r] = fmaf(s.y, w1, acc[r]);
            acc[r] = fmaf(s.z, w2, acc[r]);
            acc[r] = fmaf(s.w, w3, acc[r]);
        }
    }

    __syncthreads();                   // all GEMM reads of snf done
#pragma unroll
    for (int r = 0; r < 8; ++r)
        snf[half * 8 + r][f] = acc[r]; // snf now holds h
    __syncthreads();

    const int b  = r0 >> 11;
    const int n0 = r0 & (Nn - 1);
    const int jb = n0 >> 7;
    const int kp = (n0 & 127) >> 4;    // kpair 0..7

    // hT3 write by threads t<128 (f == t): gather 16 row-values from smem,
    // pair-interleave chunks c0 (n 0..7) / c1 (n 8..15).
    if (t < 128) {
        __half iv[16];
#pragma unroll
        for (int w = 0; w < 4; ++w) {
            iv[4 * w + 0] = __float2half(snf[2 * w][t]);
            iv[4 * w + 1] = __float2half(snf[2 * w + 1][t]);
            iv[4 * w + 2] = __float2half(snf[8 + 2 * w][t]);
            iv[4 * w + 3] = __float2half(snf[9 + 2 * w][t]);
        }
        __half* base = g_hT3 + ((((size_t)(b * NJB + jb)) * 8 + kp) * 128 + t) * 16;
        *(uint4*)base       = *(const uint4*)&iv[0];
        *(uint4*)(base + 8) = *(const uint4*)&iv[8];
    }

    // lp/lc: one (row, head) task per thread
    {
        const int rr = t >> 4;         // node-in-block 0..15
        const int h  = t & 15;
        const int slot = (rr & 1) | (((rr >> 3) & 1) << 1) | (((rr >> 1) & 3) << 2);
        const int tigs = slot >> 2, pos = slot & 3;
        const int g = n0 >> 4;
        const float* hv = &snf[rr][h * Cc];
        const float* ap = a + h * 2 * Cc;
        float lp = 0.f, lc = 0.f;
#pragma unroll
        for (int c = 0; c < Cc; ++c) {
            lp = fmaf(hv[c], ap[c],      lp);
            lc = fmaf(hv[c], ap[Cc + c], lc);
        }
        lp *= LOG2E; lc *= LOG2E;
        g_lp[(r0 + rr) * Hh + h] = lp;
        __half* fb = g_FF2 + (((size_t)b * Hh + h) * (Nn / 16) + g) * 32;
        fb[tigs * 8 + pos]     = __float2half(ex2f(lc));
        fb[tigs * 8 + 4 + pos] = __float2half(ex2f(0.2f * lc));
    }
}

// ---------------------------------------------------------------
// Kernel C: fused softmax-attention via mma.m16n8k16.  (R15 form)
// Paired layouts: 1 LDG.64 (H) + 1 LDG.128 (F) + 2 LDS.64 (adj) per k-step.
// Tail copy via TMA store from the staged fp32 tile.
// ---------------------------------------------------------------
__global__ __launch_bounds__(256, 4) void k_main(
        const __grid_constant__ CUtensorMap tmaf,
        const __grid_constant__ CUtensorMap tmat,
        float* __restrict__ out, int copy_adj) {
    extern __shared__ __align__(128) char smem[];
    __shared__ __align__(8) unsigned long long mbar[4];

    const int t    = threadIdx.x;
    const int warp = t >> 5;
    const int lane = t & 31;
    const int gid  = lane >> 2;   // 0..7
    const int tig  = lane & 3;    // 0..3

    const int bx = blockIdx.x;
    const int b  = bx >> 8;
    const int i0 = ((bx & 255) >> 1) * 16;
    const int hp = bx & 1;
    const int hh = hp * 8 + warp;
    const size_t bN = (size_t)b * Nn;
    const int yrow = (int)(bN + i0);

    if (t < 4) MBAR_INIT(s2u(&mbar[t]), 1);
    asm volatile("fence.proxy.async.shared::cta;" ::: "memory");
    __syncthreads();

    auto issue_tile = [&](int jb) {
        const int st = jb & 3;
        const uint32_t mb = s2u(&mbar[st]);
        MBAR_EXPECT(mb, TILE_BYTES);
        const uint32_t dst = s2u(smem + SO_F + st * SF_STRIDE);
        TMA2D(dst,        &tmaf, jb * 128,      yrow, mb);
        TMA2D(dst + 4096, &tmaf, jb * 128 + 64, yrow, mb);
    };

    // per-row factors, stabilized by m = leaky(lp)
    __half2 E0, E0p, E1, E1p;
    {
        const float lp0 = g_lp[(bN + i0 + gid)     * Hh + hh];
        const float lp1 = g_lp[(bN + i0 + gid + 8) * Hh + hh];
        const float m0 = fmaxf(lp0, 0.2f * lp0);
        const float m1 = fmaxf(lp1, 0.2f * lp1);
        E0  = __float2half2_rn(ex2f(lp0 - m0));
        E0p = __float2half2_rn(ex2f(0.2f * lp0 - m0));
        E1  = __float2half2_rn(ex2f(lp1 - m1));
        E1p = __float2half2_rn(ex2f(0.2f * lp1 - m1));
    }

    const __half* FFb = g_FF2 + ((size_t)b * Hh + hh) * (Nn / 16) * 32 + tig * 8;
    const char* Hbase = (const char*)g_hT3
        + (size_t)b * NJB * 32768 + (hh * 8 + gid) * 32 + tig * 8;

    float dn0 = 0.f, dn1 = 0.f, dn2 = 0.f, dn3 = 0.f;
    float dd0 = 0.f, dd1 = 0.f, dd2 = 0.f, dd3 = 0.f;
    const uint32_t ONES = 0x3C003C00u;

    // convert mapping: thread t -> row = t>>4, c = t&15 (cols 4c..4c+3)
    const int cv_row = t >> 4;
    const int cv_c   = t & 15;
    const int cv_ks  = cv_c >> 2;
    const uint32_t cv_b0 = cv_row * 32 + ((cv_c & 1) * 2) * 8 + (((cv_c >> 1) & 1)) * 4;
    const int do_tail = copy_adj && (hp == 0);

    if (t == 0) { issue_tile(0); issue_tile(1); issue_tile(2); }

    for (int jb = 0; jb < NJB; ++jb) {
        const int st = jb & 3;
        char* const sFb = smem + SO_F + st * SF_STRIDE;
        char* const sAb = smem + SO_A + (jb & 1) * SA_STRIDE;

        mbar_wait(s2u(&mbar[st]), (jb >> 2) & 1);

        // ---- convert fp32 adj tile -> paired fp16 layout ----
        {
            const float4 v0 = *(const float4*)(sFb + 16 * t);
            const float4 v1 = *(const float4*)(sFb + 16 * t + 4096);
            *(uint32_t*)(sAb + cv_ks * 512 + cv_b0)           = packh2(v0.x, v0.y);
            *(uint32_t*)(sAb + cv_ks * 512 + cv_b0 + 8)       = packh2(v0.z, v0.w);
            *(uint32_t*)(sAb + (cv_ks + 4) * 512 + cv_b0)     = packh2(v1.x, v1.y);
            *(uint32_t*)(sAb + (cv_ks + 4) * 512 + cv_b0 + 8) = packh2(v1.z, v1.w);
        }
        __syncthreads();
        if (t == 0) {
            if (do_tail) {
                asm volatile("fence.proxy.async.shared::cta;" ::: "memory");
                TMA2D_ST(&tmat, jb * 128,      yrow, s2u(sFb));
                TMA2D_ST(&tmat, jb * 128 + 64, yrow, s2u(sFb) + 4096);
                TMA_ST_COMMIT();
                TMA_ST_WAIT(1);
            }
            if (jb + 3 < NJB) issue_tile(jb + 3);
        }

        const char* Hp  = Hbase + (size_t)jb * 32768;
        const char* Ap0 = sAb + gid * 32       + tig * 8;
        const char* Ap1 = sAb + (gid + 8) * 32 + tig * 8;
        const __half* Fj = FFb + jb * 256;

#pragma unroll
        for (int ks = 0; ks < 8; ++ks) {
            const uint4 ff = *(const uint4*)(Fj + ks * 32);
            const uint2 bh = *(const uint2*)(Hp + ks * 4096);
            const uint2 a0 = *(const uint2*)(Ap0 + ks * 512);
            const uint2 a1 = *(const uint2*)(Ap1 + ks * 512);

            const __half2 w0lo = __hmax2(__hmul2(b2h(ff.x), E0),  __hmul2(b2h(ff.z), E0p));
            const __half2 w1lo = __hmax2(__hmul2(b2h(ff.x), E1),  __hmul2(b2h(ff.z), E1p));
            const __half2 w0hi = __hmax2(__hmul2(b2h(ff.y), E0),  __hmul2(b2h(ff.w), E0p));
            const __half2 w1hi = __hmax2(__hmul2(b2h(ff.y), E1),  __hmul2(b2h(ff.w), E1p));

            const uint32_t ra0 = h2b(__hmul2(w0lo, b2h(a0.x)));
            const uint32_t ra1 = h2b(__hmul2(w1lo, b2h(a1.x)));
            const uint32_t ra2 = h2b(__hmul2(w0hi, b2h(a0.y)));
            const uint32_t ra3 = h2b(__hmul2(w1hi, b2h(a1.y)));

            mma16816(dn0, dn1, dn2, dn3, ra0, ra1, ra2, ra3, bh.x, bh.y);
            mma16816(dd0, dd1, dd2, dd3, ra0, ra1, ra2, ra3, ONES, ONES);
        }
    }

    // ---- epilogue: divide and store ----
    {
        const float inv0 = 1.0f / dd0;
        const float inv1 = 1.0f / dd2;
        float2 o0 = make_float2(dn0 * inv0, dn1 * inv0);
        float2 o1 = make_float2(dn2 * inv1, dn3 * inv1);
        *(float2*)(out + (bN + i0 + gid)     * HC + hh * Cc + 2 * tig) = o0;
        *(float2*)(out + (bN + i0 + gid + 8) * HC + hh * Cc + 2 * tig) = o1;
    }

    if (t == 0 && do_tail) TMA_ST_WAIT(0);
}

// ---------------------------------------------------------------
extern "C" void kernel_launch(void* const* d_in, const int* in_sizes, int n_in,
                              void* d_out, int out_size) {
    const float* nf   = (const float*)d_in[0];
    const float* adj  = (const float*)d_in[1];
    const float* W    = (const float*)d_in[2];
    const float* bias = (const float*)d_in[3];
    const float* a    = (const float*)d_in[4];
    float* out = (float*)d_out;

    const long long outel = (long long)Bn * Nn * HC;        // 524288
    const long long adjel = (long long)Bn * Nn * Nn;        // 8388608
    const int copy_adj = ((long long)out_size >= outel + adjel) ? 1 : 0;

    // ---- TMA descriptors ----
    PFN_tmencode pfn = nullptr;
    cudaDriverEntryPointQueryResult qr;
    cudaGetDriverEntryPoint("cuTensorMapEncodeTiled", (void**)&pfn,
                            cudaEnableDefault, &qr);

    CUtensorMap tmaf, tmat;
    {
        cuuint64_t dims[2]    = { (cuuint64_t)Nn, (cuuint64_t)(Bn * Nn) };
        cuuint64_t strides[1] = { (cuuint64_t)Nn * 4 };
        cuuint32_t box[2]     = { 64, 16 };
        cuuint32_t estr[2]    = { 1, 1 };
        pfn(&tmaf, CU_TENSOR_MAP_DATA_TYPE_FLOAT32, 2, (void*)adj, dims, strides,
            box, estr, CU_TENSOR_MAP_INTERLEAVE_NONE, CU_TENSOR_MAP_SWIZZLE_NONE,
            CU_TENSOR_MAP_L2_PROMOTION_L2_128B, CU_TENSOR_MAP_FLOAT_OOB_FILL_NONE);
        pfn(&tmat, CU_TENSOR_MAP_DATA_TYPE_FLOAT32, 2, (void*)(out + outel),
            dims, strides, box, estr,
            CU_TENSOR_MAP_INTERLEAVE_NONE, CU_TENSOR_MAP_SWIZZLE_NONE,
            CU_TENSOR_MAP_L2_PROMOTION_L2_128B, CU_TENSOR_MAP_FLOAT_OOB_FILL_NONE);
    }

    cudaFuncSetAttribute(k_main, cudaFuncAttributeMaxDynamicSharedMemorySize,
                         SMEM_BYTES);

    k_proj<<<Bn * Nn / 16, 256>>>(nf, W, bias, a);
    k_main<<<Bn * 256, 256, SMEM_BYTES>>>(tmaf, tmat, out, copy_adj);
}